// round 12
// baseline (speedup 1.0000x reference)
#include <cuda_runtime.h>
#include <cuda_bf16.h>

// KL(p||q) for diagonal Gaussians, mean over batch.
// R8 structure (best: pure-STG primary + PDL sleep-wait finish) with one
// change: the primary's loop takes a compile-time-bounded fast path when
// n4 == 2^21 (the fixed problem shape) -> 8 exact iterations, unroll 2,
// 8 front-batched LDG.128, no guards. Generic runtime loop as fallback.
// Deterministic: fixed grid, fixed reduction order.

#define NBLOCKS 1024
#define NTHREADS 256
#define FIN_THREADS 1024
#define N4_FIXED (1 << 21)                 // 8388608 / 4
#define STRIDE_FIXED (NBLOCKS * NTHREADS)  // 262144
#define ITERS_FIXED (N4_FIXED / STRIDE_FIXED)  // 8

__device__ float g_partials[NBLOCKS];

__device__ __forceinline__ float kl_vec4(float4 a, float4 b, float4 c, float4 d)
{
    float r;
    {
        float lr = d.x - b.x;
        float dm = a.x - c.x;
        r = lr + __expf(-lr) + dm * dm * __expf(-d.x) - 1.0f;
    }
    {
        float lr = d.y - b.y;
        float dm = a.y - c.y;
        r += lr + __expf(-lr) + dm * dm * __expf(-d.y) - 1.0f;
    }
    {
        float lr = d.z - b.z;
        float dm = a.z - c.z;
        r += lr + __expf(-lr) + dm * dm * __expf(-d.z) - 1.0f;
    }
    {
        float lr = d.w - b.w;
        float dm = a.w - c.w;
        r += lr + __expf(-lr) + dm * dm * __expf(-d.w) - 1.0f;
    }
    return r;
}

__global__ __launch_bounds__(NTHREADS) void kl_partial_kernel(
    const float* __restrict__ p_mu,
    const float* __restrict__ p_lv,
    const float* __restrict__ q_mu,
    const float* __restrict__ q_lv,
    int n4)
{
    cudaTriggerProgrammaticLaunchCompletion();

    const float4* pm4 = reinterpret_cast<const float4*>(p_mu);
    const float4* pl4 = reinterpret_cast<const float4*>(p_lv);
    const float4* qm4 = reinterpret_cast<const float4*>(q_mu);
    const float4* ql4 = reinterpret_cast<const float4*>(q_lv);

    const int tid = blockIdx.x * blockDim.x + threadIdx.x;
    float acc = 0.0f;

    if (n4 == N4_FIXED) {
        // Fast path: compile-time trip count, no guards.
        #pragma unroll 2
        for (int k = 0; k < ITERS_FIXED; ++k) {
            const int i = tid + k * STRIDE_FIXED;
            float4 a = pm4[i];
            float4 b = pl4[i];
            float4 c = qm4[i];
            float4 d = ql4[i];
            acc += kl_vec4(a, b, c, d);
        }
    } else {
        // Generic fallback (uniform branch).
        int stride = gridDim.x * blockDim.x;
        for (int i = tid; i < n4; i += stride) {
            acc += kl_vec4(pm4[i], pl4[i], qm4[i], ql4[i]);
        }
    }

    // Block reduce
    #pragma unroll
    for (int off = 16; off > 0; off >>= 1)
        acc += __shfl_down_sync(0xFFFFFFFFu, acc, off);

    __shared__ float smem[NTHREADS / 32];
    int lane = threadIdx.x & 31;
    int warp = threadIdx.x >> 5;
    if (lane == 0) smem[warp] = acc;
    __syncthreads();

    if (warp == 0) {
        acc = (lane < NTHREADS / 32) ? smem[lane] : 0.0f;
        #pragma unroll
        for (int off = 4; off > 0; off >>= 1)
            acc += __shfl_down_sync(0xFFFFFFFFu, acc, off);
        if (lane == 0) g_partials[blockIdx.x] = acc;
    }
}

__global__ __launch_bounds__(FIN_THREADS) void kl_finish_kernel(float* out, float scale)
{
    // PDL: launched early, HW-sleeps until the primary grid fully retires.
    cudaGridDependencySynchronize();

    float acc = g_partials[threadIdx.x];

    #pragma unroll
    for (int off = 16; off > 0; off >>= 1)
        acc += __shfl_down_sync(0xFFFFFFFFu, acc, off);

    __shared__ float smem[32];
    int lane = threadIdx.x & 31;
    int warp = threadIdx.x >> 5;
    if (lane == 0) smem[warp] = acc;
    __syncthreads();

    if (warp == 0) {
        acc = smem[lane];
        #pragma unroll
        for (int off = 16; off > 0; off >>= 1)
            acc += __shfl_down_sync(0xFFFFFFFFu, acc, off);
        if (lane == 0) out[0] = acc * scale;
    }
}

extern "C" void kernel_launch(void* const* d_in, const int* in_sizes, int n_in,
                              void* d_out, int out_size)
{
    const float* p_mu = (const float*)d_in[0];
    const float* p_lv = (const float*)d_in[1];
    const float* q_mu = (const float*)d_in[2];
    const float* q_lv = (const float*)d_in[3];
    float* out = (float*)d_out;

    int n  = in_sizes[0];     // B*D
    int n4 = n >> 2;
    int B  = n / 512;         // D = 512
    float scale = 0.5f / (float)B;

    kl_partial_kernel<<<NBLOCKS, NTHREADS>>>(p_mu, p_lv, q_mu, q_lv, n4);

    cudaLaunchConfig_t cfg = {};
    cfg.gridDim  = dim3(1, 1, 1);
    cfg.blockDim = dim3(FIN_THREADS, 1, 1);
    cfg.dynamicSmemBytes = 0;
    cfg.stream = 0;
    cudaLaunchAttribute attrs[1];
    attrs[0].id = cudaLaunchAttributeProgrammaticStreamSerialization;
    attrs[0].val.programmaticStreamSerializationAllowed = 1;
    cfg.attrs = attrs;
    cfg.numAttrs = 1;
    cudaLaunchKernelEx(&cfg, kl_finish_kernel, out, scale);
}

// round 13
// speedup vs baseline: 1.0922x; 1.0922x over previous
#include <cuda_runtime.h>
#include <cuda_bf16.h>

// KL(p||q) for diagonal Gaussians, mean over batch.  FINAL (R8 lock-in).
// Two kernels: primary = plain grid-stride float4 loop (1024x256; the only
// loop form ptxas schedules at ~5.9 TB/s — all 5 hand-tuned variants lost),
// finish = PDL-launched 1-block reduction that HW-sleeps in
// cudaGridDependencySynchronize(), overlapping its launch latency with the
// primary's execution. Deterministic: fixed grid, fixed reduction order.

#define NBLOCKS 1024
#define NTHREADS 256

__device__ float g_partials[NBLOCKS];

__global__ __launch_bounds__(NTHREADS) void kl_partial_kernel(
    const float* __restrict__ p_mu,
    const float* __restrict__ p_lv,
    const float* __restrict__ q_mu,
    const float* __restrict__ q_lv,
    int n4)
{
    // Let the dependent (finish) kernel launch immediately; it will block in
    // cudaGridDependencySynchronize() until this grid completes.
    cudaTriggerProgrammaticLaunchCompletion();

    const float4* pm4 = reinterpret_cast<const float4*>(p_mu);
    const float4* pl4 = reinterpret_cast<const float4*>(p_lv);
    const float4* qm4 = reinterpret_cast<const float4*>(q_mu);
    const float4* ql4 = reinterpret_cast<const float4*>(q_lv);

    float acc = 0.0f;
    int stride = gridDim.x * blockDim.x;
    for (int i = blockIdx.x * blockDim.x + threadIdx.x; i < n4; i += stride) {
        float4 a = pm4[i];
        float4 b = pl4[i];
        float4 c = qm4[i];
        float4 d = ql4[i];

        {
            float lr = d.x - b.x;
            float dm = a.x - c.x;
            acc += lr + __expf(-lr) + dm * dm * __expf(-d.x) - 1.0f;
        }
        {
            float lr = d.y - b.y;
            float dm = a.y - c.y;
            acc += lr + __expf(-lr) + dm * dm * __expf(-d.y) - 1.0f;
        }
        {
            float lr = d.z - b.z;
            float dm = a.z - c.z;
            acc += lr + __expf(-lr) + dm * dm * __expf(-d.z) - 1.0f;
        }
        {
            float lr = d.w - b.w;
            float dm = a.w - c.w;
            acc += lr + __expf(-lr) + dm * dm * __expf(-d.w) - 1.0f;
        }
    }

    // warp reduce
    #pragma unroll
    for (int off = 16; off > 0; off >>= 1)
        acc += __shfl_down_sync(0xFFFFFFFFu, acc, off);

    __shared__ float smem[NTHREADS / 32];
    int lane = threadIdx.x & 31;
    int warp = threadIdx.x >> 5;
    if (lane == 0) smem[warp] = acc;
    __syncthreads();

    if (warp == 0) {
        acc = (lane < NTHREADS / 32) ? smem[lane] : 0.0f;
        #pragma unroll
        for (int off = 4; off > 0; off >>= 1)
            acc += __shfl_down_sync(0xFFFFFFFFu, acc, off);
        if (lane == 0) g_partials[blockIdx.x] = acc;
    }
}

__global__ __launch_bounds__(1024) void kl_finish_kernel(float* out, float scale)
{
    // Launched early via PDL; HW-sleep here until the primary grid (and all
    // its memory writes) completes.
    cudaGridDependencySynchronize();

    float acc = g_partials[threadIdx.x];

    #pragma unroll
    for (int off = 16; off > 0; off >>= 1)
        acc += __shfl_down_sync(0xFFFFFFFFu, acc, off);

    __shared__ float smem[32];
    int lane = threadIdx.x & 31;
    int warp = threadIdx.x >> 5;
    if (lane == 0) smem[warp] = acc;
    __syncthreads();

    if (warp == 0) {
        acc = smem[lane];
        #pragma unroll
        for (int off = 16; off > 0; off >>= 1)
            acc += __shfl_down_sync(0xFFFFFFFFu, acc, off);
        if (lane == 0) out[0] = acc * scale;
    }
}

extern "C" void kernel_launch(void* const* d_in, const int* in_sizes, int n_in,
                              void* d_out, int out_size)
{
    const float* p_mu = (const float*)d_in[0];
    const float* p_lv = (const float*)d_in[1];
    const float* q_mu = (const float*)d_in[2];
    const float* q_lv = (const float*)d_in[3];
    float* out = (float*)d_out;

    int n  = in_sizes[0];     // B*D
    int n4 = n >> 2;
    int B  = n / 512;         // D = 512
    float scale = 0.5f / (float)B;

    kl_partial_kernel<<<NBLOCKS, NTHREADS>>>(p_mu, p_lv, q_mu, q_lv, n4);

    // Finish kernel with programmatic dependent launch: overlaps its launch
    // latency with the primary kernel's execution.
    cudaLaunchConfig_t cfg = {};
    cfg.gridDim  = dim3(1, 1, 1);
    cfg.blockDim = dim3(1024, 1, 1);
    cfg.dynamicSmemBytes = 0;
    cfg.stream = 0;
    cudaLaunchAttribute attrs[1];
    attrs[0].id = cudaLaunchAttributeProgrammaticStreamSerialization;
    attrs[0].val.programmaticStreamSerializationAllowed = 1;
    cfg.attrs = attrs;
    cfg.numAttrs = 1;
    cudaLaunchKernelEx(&cfg, kl_finish_kernel, out, scale);
}